// round 3
// baseline (speedup 1.0000x reference)
#include <cuda_runtime.h>

#define Nn 5000
#define Ee 80000
#define FIN 32
#define Dd 64
#define P1n 256
#define P2n 32
#define Hh 256
#define Mm 5288
#define SCALE 1.4763057f

// ---------------- scratch (static, no allocation) ----------------
__device__ float g_z[Nn * Dd];
__device__ float g_XW1[Nn * Dd];
__device__ float g_P1[Nn * P1n];
__device__ float g_S1[Nn * P1n];
__device__ float g_AS1[Nn * P1n];
__device__ float g_ze1[Nn * Dd];
__device__ unsigned int g_bitmap[(Nn * Nn + 31) / 32];
__device__ unsigned char g_mask[Ee];
__device__ int g_cnt[Nn];
__device__ int g_fill[Nn];
__device__ int g_rowptr[Nn + 1];
__device__ int g_cols[Ee];
__device__ float g_colE[P1n], g_colEV[P1n], g_invZ[P1n];
__device__ float g_x1[P1n * Dd];
__device__ float g_y1[P1n];
__device__ float g_A2[P1n * P1n];
__device__ float g_P2[P1n * P2n];
__device__ float g_S2[P1n * P2n];
__device__ float g_XW2[P1n * Dd];
__device__ float g_ze2[P1n * Dd];
__device__ float g_x2[P2n * Dd];
__device__ float g_y2[P2n];
__device__ float g_c[Hh], g_q[Hh], g_w0[Hh];
__device__ float g_acc[4];  // [0]=ent, [1]=sum(u-y)^2, [2]=sum(res^2)

// ---------------- zero everything that is accumulated ----------------
__global__ void zero_all() {
    int i = blockIdx.x * blockDim.x + threadIdx.x;
    int st = gridDim.x * blockDim.x;
    const int BW = (Nn * Nn + 31) / 32;
    for (int k = i; k < BW; k += st) g_bitmap[k] = 0u;
    for (int k = i; k < Nn; k += st) { g_cnt[k] = 0; g_fill[k] = 0; }
    for (int k = i; k < P1n; k += st) { g_colE[k] = 0.f; g_colEV[k] = 0.f; g_y1[k] = 0.f; }
    for (int k = i; k < P1n * Dd; k += st) g_x1[k] = 0.f;
    for (int k = i; k < P1n * P1n; k += st) g_A2[k] = 0.f;
    if (i < 4) g_acc[i] = 0.f;
}

// ---------------- edge dedup + CSR build ----------------
__global__ void edge_mask(const int* __restrict__ adj) {
    int e = blockIdx.x * blockDim.x + threadIdx.x;
    if (e >= Ee) return;
    int r0 = adj[e], r1 = adj[Ee + e];
    unsigned int key = (unsigned int)r0 * (unsigned int)Nn + (unsigned int)r1;
    unsigned int bit = 1u << (key & 31u);
    unsigned int old = atomicOr(&g_bitmap[key >> 5], bit);
    bool uniq = ((old & bit) == 0u);
    g_mask[e] = uniq ? 1 : 0;
    if (uniq) atomicAdd(&g_cnt[r0], 1);
}

__global__ void scan_k() {  // 1 block, 1024 threads: exclusive scan of g_cnt -> g_rowptr
    __shared__ int ssum[1024];
    int t = threadIdx.x;
    int loc[5];
    int s = 0;
#pragma unroll
    for (int i = 0; i < 5; i++) {
        int idx = t * 5 + i;
        int v = (idx < Nn) ? g_cnt[idx] : 0;
        loc[i] = s; s += v;
    }
    ssum[t] = s;
    __syncthreads();
    for (int off = 1; off < 1024; off <<= 1) {
        int v = (t >= off) ? ssum[t - off] : 0;
        __syncthreads();
        ssum[t] += v;
        __syncthreads();
    }
    int offset = (t > 0) ? ssum[t - 1] : 0;
#pragma unroll
    for (int i = 0; i < 5; i++) {
        int idx = t * 5 + i;
        if (idx < Nn) g_rowptr[idx] = offset + loc[i];
    }
    if (t == 1023) g_rowptr[Nn] = ssum[1023];
}

__global__ void csr_fill(const int* __restrict__ adj) {
    int e = blockIdx.x * blockDim.x + threadIdx.x;
    if (e >= Ee) return;
    if (!g_mask[e]) return;
    int r0 = adj[e], r1 = adj[Ee + e];
    int pos = atomicAdd(&g_fill[r0], 1);
    g_cols[g_rowptr[r0] + pos] = r1;
}

// ---------------- fused encode: z = tanh(x0 W_enc)*SCALE ; XW1 = z W_emb1 ; P1 = (z W_pool1)*SCALE ----------------
__global__ void encode_fused(const float* __restrict__ x0, const float* __restrict__ Wenc,
                             const float* __restrict__ Wemb, const float* __restrict__ Wp) {
    __shared__ float xsh[32][FIN];
    __shared__ float zsh[32][Dd];
    int r0 = blockIdx.x * 32;
    int tid = threadIdx.x;
    for (int idx = tid; idx < 32 * FIN; idx += 256) {
        int r = idx / FIN, c = idx % FIN;
        int row = r0 + r;
        xsh[r][c] = (row < Nn) ? x0[row * FIN + c] : 0.f;
    }
    __syncthreads();
    for (int idx = tid; idx < 32 * Dd; idx += 256) {
        int r = idx / Dd, d = idx % Dd;
        float a = 0.f;
#pragma unroll
        for (int k = 0; k < FIN; k++) a += xsh[r][k] * Wenc[k * (Dd + 3) + d];
        float v = tanhf(a) * SCALE;
        zsh[r][d] = v;
        int row = r0 + r;
        if (row < Nn) g_z[row * Dd + d] = v;
    }
    __syncthreads();
    for (int idx = tid; idx < 32 * Dd; idx += 256) {
        int r = idx / Dd, d = idx % Dd;
        int row = r0 + r;
        if (row < Nn) {
            float a = 0.f;
#pragma unroll
            for (int k = 0; k < Dd; k++) a += zsh[r][k] * Wemb[k * Dd + d];
            g_XW1[row * Dd + d] = a;
        }
    }
    int p = tid;
    for (int r = 0; r < 32; r++) {
        int row = r0 + r;
        if (row >= Nn) break;
        float a = 0.f;
#pragma unroll
        for (int k = 0; k < Dd; k++) a += zsh[r][k] * Wp[k * P1n + p];
        g_P1[row * P1n + p] = a * SCALE;
    }
}

// ---------------- column softmax level 1 (no max-sub: |v| bounded ~15) ----------------
__global__ void colsum1() {
    int p = threadIdx.x;
    int r0 = blockIdx.x * 32;
    float se = 0.f, sev = 0.f;
    for (int r = 0; r < 32; r++) {
        int row = r0 + r;
        if (row >= Nn) break;
        float v = g_P1[row * P1n + p];
        float e = __expf(v);
        se += e; sev += e * v;
    }
    atomicAdd(&g_colE[p], se);
    atomicAdd(&g_colEV[p], sev);
}

__global__ void finalize1() {  // 1 block, 256 threads
    int p = threadIdx.x;
    float Z = g_colE[p];
    g_invZ[p] = 1.f / Z;
    float ent = __logf(Z) - g_colEV[p] / Z;  // column entropy
    __shared__ float sh[8];
#pragma unroll
    for (int off = 16; off; off >>= 1) ent += __shfl_down_sync(0xffffffffu, ent, off);
    if ((p & 31) == 0) sh[p >> 5] = ent;
    __syncthreads();
    if (p == 0) {
        float s = 0.f;
        for (int w = 0; w < 8; w++) s += sh[w];
        atomicAdd(&g_acc[0], s / ((float)Nn * (float)P1n));
    }
}

__global__ void norm1() {
    int p = threadIdx.x;
    int r0 = blockIdx.x * 32;
    for (int r = 0; r < 32; r++) {
        int row = r0 + r;
        if (row >= Nn) break;
        float v = g_P1[row * P1n + p];
        g_S1[row * P1n + p] = __expf(v) * g_invZ[p];
    }
}

// ---------------- sparse gathers: ze1 = tanh(A @ XW1), AS1 = A @ S1 ----------------
__global__ void gatherAX() {
    int i = blockIdx.x, d = threadIdx.x;
    int s = g_rowptr[i], e = g_rowptr[i + 1];
    float a = 0.f;
    for (int k = s; k < e; k++) {
        int j = g_cols[k];
        a += g_XW1[j * Dd + d];
    }
    g_ze1[i * Dd + d] = tanhf(a);
}

__global__ void gatherAS() {
    int i = blockIdx.x, p = threadIdx.x;
    int s = g_rowptr[i], e = g_rowptr[i + 1];
    float a = 0.f;
    for (int k = s; k < e; k++) {
        int j = g_cols[k];
        a += g_S1[j * P1n + p];
    }
    g_AS1[i * P1n + p] = a;
}

// ---------------- split-K pooled GEMMs: C = S1^T B (* scale); MODE0 also y1 = S1^T y ----------------
template <int MODE>
__global__ void pool_gemm(const float* __restrict__ yin) {
    const float* __restrict__ B = (MODE == 0) ? g_ze1 : g_AS1;
    float* __restrict__ C = (MODE == 0) ? g_x1 : g_A2;
    const int bcols = (MODE == 0) ? Dd : P1n;
    const float scl = (MODE == 0) ? ((float)P1n / (float)Nn) : 1.f;
    const int KB = 40;
    const int chunk = (Nn + KB - 1) / KB;  // 125
    int rbeg = blockIdx.x * chunk;
    int rend = rbeg + chunk; if (rend > Nn) rend = Nn;
    int d0 = blockIdx.y * 64;
    __shared__ float Ssh[8][P1n];
    __shared__ __align__(16) float Bsh[8][Dd];
    __shared__ float ysh[8];
    int tid = threadIdx.x;
    float acc[64];
#pragma unroll
    for (int d = 0; d < 64; d++) acc[d] = 0.f;
    float accY = 0.f;
    for (int t0 = rbeg; t0 < rend; t0 += 8) {
#pragma unroll
        for (int l = 0; l < 8; l++) {
            int row = t0 + l;
            Ssh[l][tid] = (row < rend) ? g_S1[row * P1n + tid] : 0.f;
        }
        for (int idx = tid; idx < 8 * Dd; idx += 256) {
            int r = idx / Dd, c = idx % Dd;
            int row = t0 + r;
            Bsh[r][c] = (row < rend) ? B[row * bcols + d0 + c] : 0.f;
        }
        if (MODE == 0 && tid < 8) {
            int row = t0 + tid;
            ysh[tid] = (row < rend) ? yin[row] : 0.f;
        }
        __syncthreads();
#pragma unroll
        for (int r = 0; r < 8; r++) {
            float a = Ssh[r][tid];
            if (MODE == 0) accY += a * ysh[r];
            const float4* b4 = (const float4*)Bsh[r];
#pragma unroll
            for (int d = 0; d < 16; d++) {
                float4 b = b4[d];
                acc[4 * d + 0] += a * b.x;
                acc[4 * d + 1] += a * b.y;
                acc[4 * d + 2] += a * b.z;
                acc[4 * d + 3] += a * b.w;
            }
        }
        __syncthreads();
    }
    const int ccols = bcols;
#pragma unroll
    for (int d = 0; d < 64; d++) atomicAdd(&C[tid * ccols + d0 + d], acc[d] * scl);
    if (MODE == 0) atomicAdd(&g_y1[tid], accY * scl);
}

// ---------------- level 2 (tiny, 256-sized) ----------------
__global__ void level2_mats(const float* __restrict__ Wp2, const float* __restrict__ Wemb2) {
    int i = blockIdx.x, tid = threadIdx.x;
    __shared__ float xsh[Dd];
    if (tid < Dd) xsh[tid] = g_x1[i * Dd + tid];
    __syncthreads();
    if (tid < P2n) {
        float a = 0.f;
#pragma unroll
        for (int k = 0; k < Dd; k++) a += xsh[k] * Wp2[k * P2n + tid];
        g_P2[i * P2n + tid] = a * SCALE;
    } else if (tid < P2n + Dd) {
        int d = tid - P2n;
        float a = 0.f;
#pragma unroll
        for (int k = 0; k < Dd; k++) a += xsh[k] * Wemb2[k * Dd + d];
        g_XW2[i * Dd + d] = a;
    }
}

__global__ void softmax2() {  // grid 32 (col), 256 threads (rows)
    int p = blockIdx.x, i = threadIdx.x;
    float v = g_P2[i * P2n + p];
    float e = __expf(v);
    float se = e, sev = e * v;
    __shared__ float shE[8], shEV[8];
    __shared__ float sZ;
#pragma unroll
    for (int off = 16; off; off >>= 1) {
        se += __shfl_down_sync(0xffffffffu, se, off);
        sev += __shfl_down_sync(0xffffffffu, sev, off);
    }
    if ((i & 31) == 0) { shE[i >> 5] = se; shEV[i >> 5] = sev; }
    __syncthreads();
    if (i == 0) {
        float Z = 0.f, EV = 0.f;
        for (int w = 0; w < 8; w++) { Z += shE[w]; EV += shEV[w]; }
        sZ = Z;
        atomicAdd(&g_acc[0], (__logf(Z) - EV / Z) / ((float)P1n * (float)P2n));
    }
    __syncthreads();
    g_S2[i * P2n + p] = e / sZ;
}

__global__ void ax2() {  // ze2 = tanh(A2 @ XW2)
    int i = blockIdx.x, d = threadIdx.x;
    float a = 0.f;
    for (int k = 0; k < P1n; k++) a += g_A2[i * P1n + k] * g_XW2[k * Dd + d];
    g_ze2[i * Dd + d] = tanhf(a);
}

__global__ void pool2() {  // x2 = S2^T ze2 * (32/256); y2 = S2^T y1 * (32/256)
    int p = blockIdx.x, d = threadIdx.x;
    float a = 0.f, ay = 0.f;
    for (int k = 0; k < P1n; k++) {
        float s = g_S2[k * P2n + p];
        a += s * g_ze2[k * Dd + d];
        ay += s * g_y1[k];
    }
    const float scl = (float)P2n / (float)P1n;
    g_x2[p * Dd + d] = a * scl;
    if (d == 0) g_y2[p] = ay * scl;
}

// ---------------- decoder precompute: c_h, q_h, w0_h ----------------
__global__ void dec_prep(const float* __restrict__ t, const float* __restrict__ W1,
                         const float* __restrict__ b1) {
    int h = threadIdx.x;
    float t0 = t[0];
    float tx[6];
    tx[0] = t0 * 1e-2f;
    tx[1] = t0 * 1e-3f;
    tx[2] = t0 * 1e-4f;
    tx[3] = logf(t0 * 100.f + 1.f);
    tx[4] = logf(t0 * 10.f + 1.f);
    tx[5] = logf(t0 + 1.f);
    float c = b1[h];
#pragma unroll
    for (int k = 0; k < 6; k++) c += W1[k * Hh + h] * tx[k];
    float q = 0.f;
#pragma unroll
    for (int k = 1; k < 9; k++) { float w = W1[k * Hh + h]; q += w * w; }
    g_c[h] = c;
    g_q[h] = q;
    g_w0[h] = W1[h];
}

// ---------------- decoder + losses (8 rows per block) ----------------
__global__ void decoder(const float* __restrict__ W1, const float* __restrict__ W2,
                        const float* __restrict__ b2, const float* __restrict__ yin) {
    int base = blockIdx.x * 8;
    int h = threadIdx.x;
    __shared__ float zsh[8][Dd];
    __shared__ float ysh[8];
    __shared__ float sU[8], sR[8];
    for (int idx = h; idx < 8 * Dd; idx += 256) {
        int r = idx / Dd, j = idx % Dd;
        int m = base + r;
        float v;
        if (m < Nn) v = g_z[m * Dd + j];
        else if (m < Nn + P1n) v = g_x1[(m - Nn) * Dd + j];
        else v = g_x2[(m - Nn - P1n) * Dd + j];
        zsh[r][j] = v;
    }
    if (h < 8) {
        int m = base + h;
        ysh[h] = (m < Nn) ? yin[m] : (m < Nn + P1n) ? g_y1[m - Nn] : g_y2[m - Nn - P1n];
    }
    __syncthreads();
    float c = g_c[h];
    float acc[8];
#pragma unroll
    for (int r = 0; r < 8; r++) acc[r] = c;
#pragma unroll 4
    for (int j = 0; j < Dd; j++) {
        float w = W1[(9 + j) * Hh + h];
#pragma unroll
        for (int r = 0; r < 8; r++) acc[r] += w * zsh[r][j];
    }
    float w2 = W2[h], w0 = g_w0[h], q = g_q[h];
    float b2v = b2[0];
    for (int r = 0; r < 8; r++) {
        float th = tanhf(acc[r]);
        float s = 1.f - th * th;
        float up = w2 * th;
        float rp = w2 * s * (w0 + 2.f * th * q);
#pragma unroll
        for (int off = 16; off; off >>= 1) {
            up += __shfl_down_sync(0xffffffffu, up, off);
            rp += __shfl_down_sync(0xffffffffu, rp, off);
        }
        if ((h & 31) == 0) { sU[h >> 5] = up; sR[h >> 5] = rp; }
        __syncthreads();
        if (h == 0) {
            float u = b2v, rr = 0.f;
            for (int w = 0; w < 8; w++) { u += sU[w]; rr += sR[w]; }
            float dd = u - ysh[r];
            atomicAdd(&g_acc[1], dd * dd);
            atomicAdd(&g_acc[2], rr * rr);
        }
        __syncthreads();
    }
}

__global__ void fin(float* __restrict__ out) {
    out[0] = g_acc[1] / (float)Mm + g_acc[2] / (float)Mm + g_acc[0];
}

// ---------------- launch ----------------
extern "C" void kernel_launch(void* const* d_in, const int* in_sizes, int n_in,
                              void* d_out, int out_size) {
    const float* x0 = (const float*)d_in[0];
    const int* adj = (const int*)d_in[1];
    const float* t = (const float*)d_in[2];
    const float* y = (const float*)d_in[3];
    const float* Wenc = (const float*)d_in[4];
    const float* Wp1 = (const float*)d_in[5];
    const float* Wp2 = (const float*)d_in[6];
    const float* Wemb1 = (const float*)d_in[7];
    const float* Wemb2 = (const float*)d_in[8];
    const float* W1 = (const float*)d_in[9];
    const float* b1 = (const float*)d_in[10];
    const float* W2 = (const float*)d_in[11];
    const float* b2 = (const float*)d_in[12];
    float* out = (float*)d_out;

    zero_all<<<256, 256>>>();
    edge_mask<<<(Ee + 255) / 256, 256>>>(adj);
    scan_k<<<1, 1024>>>();
    csr_fill<<<(Ee + 255) / 256, 256>>>(adj);
    encode_fused<<<(Nn + 31) / 32, 256>>>(x0, Wenc, Wemb1, Wp1);
    colsum1<<<(Nn + 31) / 32, 256>>>();
    finalize1<<<1, 256>>>();
    norm1<<<(Nn + 31) / 32, 256>>>();
    gatherAX<<<Nn, 64>>>();
    gatherAS<<<Nn, 256>>>();
    pool_gemm<0><<<dim3(40, 1), 256>>>(y);
    pool_gemm<1><<<dim3(40, 4), 256>>>(nullptr);
    level2_mats<<<P1n, 96>>>(Wp2, Wemb2);
    softmax2<<<P2n, 256>>>();
    ax2<<<P1n, Dd>>>();
    pool2<<<P2n, Dd>>>();
    dec_prep<<<1, Hh>>>(t, W1, b1);
    decoder<<<Mm / 8, 256>>>(W1, W2, b2, y);
    fin<<<1, 1>>>(out);
}

// round 4
// speedup vs baseline: 1.1311x; 1.1311x over previous
#include <cuda_runtime.h>

#define Nn 5000
#define Ee 80000
#define FIN 32
#define Dd 64
#define P1n 256
#define P2n 32
#define Hh 256
#define Mm 5288
#define ELLW 128
#define SCALE 1.4763057f

typedef unsigned long long u64;

// ---------------- packed f32x2 helpers ----------------
__device__ __forceinline__ void fma2(u64& acc, u64 b, u64 a) {
    asm("fma.rn.f32x2 %0, %1, %2, %0;" : "+l"(acc) : "l"(b), "l"(a));
}
__device__ __forceinline__ u64 pk2(float lo, float hi) {
    u64 r; asm("mov.b64 %0, {%1, %2};" : "=l"(r) : "f"(lo), "f"(hi)); return r;
}
__device__ __forceinline__ void unpk(u64 v, float& a, float& b) {
    asm("mov.b64 {%0, %1}, %2;" : "=f"(a), "=f"(b) : "l"(v));
}
__device__ __forceinline__ float sum2(u64 v) {
    float a, b; unpk(v, a, b); return a + b;
}

// ---------------- scratch (static, no allocation) ----------------
__device__ __align__(16) float g_z[Nn * Dd];
__device__ __align__(16) float g_XW1[Nn * Dd];
__device__ __align__(16) float g_E1[Nn * P1n];    // exp(P1) unnormalized
__device__ __align__(16) float g_AS1[Nn * P1n];   // A @ E1 (unscaled)
__device__ __align__(16) float g_ze1[Nn * Dd];
__device__ unsigned int g_bitmap[(Nn * Nn + 31) / 32];
__device__ int g_cnt[Nn];
__device__ int g_ell[Nn * ELLW];
__device__ float g_colE[P1n], g_colEV[P1n], g_invZ[P1n];
__device__ __align__(16) float g_x1[P1n * Dd];
__device__ float g_y1[P1n];
__device__ __align__(16) float g_A2[P1n * P1n];
__device__ __align__(16) float g_S2[P1n * P2n];
__device__ __align__(16) float g_ze2[P1n * Dd];
__device__ float g_c[Hh], g_q[Hh], g_w0[Hh];
__device__ float g_acc[4];   // [0]=ent, [1]=sum(u-y)^2, [2]=sum(res^2)
__device__ unsigned int g_done;

// ---------------- kernel 1: zero accumulators + decoder prep ----------------
__global__ void zero_all(const float* __restrict__ t, const float* __restrict__ W1,
                         const float* __restrict__ b1) {
    int i = blockIdx.x * blockDim.x + threadIdx.x;
    int st = gridDim.x * blockDim.x;
    const int BW = (Nn * Nn + 31) / 32;       // 781250
    const int BW4 = BW / 4;                    // 195312
    uint4* bm4 = (uint4*)g_bitmap;
    uint4 z4 = make_uint4(0u, 0u, 0u, 0u);
    for (int k = i; k < BW4; k += st) bm4[k] = z4;
    if (i < BW - BW4 * 4) g_bitmap[BW4 * 4 + i] = 0u;
    for (int k = i; k < Nn; k += st) g_cnt[k] = 0;
    for (int k = i; k < P1n; k += st) { g_colE[k] = 0.f; g_colEV[k] = 0.f; g_y1[k] = 0.f; }
    for (int k = i; k < P1n * Dd; k += st) g_x1[k] = 0.f;
    for (int k = i; k < P1n * P1n; k += st) g_A2[k] = 0.f;
    if (i == 0) { g_acc[0] = g_acc[1] = g_acc[2] = g_acc[3] = 0.f; g_done = 0u; }
    // decoder precompute (block 0, threads 0..255 = h)
    if (blockIdx.x == 0) {
        int h = threadIdx.x;
        float t0 = t[0];
        float tx[6];
        tx[0] = t0 * 1e-2f;
        tx[1] = t0 * 1e-3f;
        tx[2] = t0 * 1e-4f;
        tx[3] = logf(t0 * 100.f + 1.f);
        tx[4] = logf(t0 * 10.f + 1.f);
        tx[5] = logf(t0 + 1.f);
        float c = b1[h];
#pragma unroll
        for (int k = 0; k < 6; k++) c += W1[k * Hh + h] * tx[k];
        float q = 0.f;
#pragma unroll
        for (int k = 1; k < 9; k++) { float w = W1[k * Hh + h]; q += w * w; }
        g_c[h] = c; g_q[h] = q; g_w0[h] = W1[h];
    }
}

// ---------------- kernel 2: edge dedup + ELL build ----------------
__global__ void edge_build(const int* __restrict__ adj) {
    int e = blockIdx.x * blockDim.x + threadIdx.x;
    if (e >= Ee) return;
    int r0 = adj[e], r1 = adj[Ee + e];
    unsigned int key = (unsigned int)r0 * (unsigned int)Nn + (unsigned int)r1;
    unsigned int bit = 1u << (key & 31u);
    unsigned int old = atomicOr(&g_bitmap[key >> 5], bit);
    if ((old & bit) == 0u) {
        int pos = atomicAdd(&g_cnt[r0], 1);
        if (pos < ELLW) g_ell[r0 * ELLW + pos] = r1;
    }
}

// ---------------- kernel 3: encode + XW1 + exp(P1) + column sums ----------------
__global__ void encode_fused(const float* __restrict__ x0, const float* __restrict__ Wenc,
                             const float* __restrict__ Wemb, const float* __restrict__ Wp) {
    __shared__ float xsh[32][FIN];
    __shared__ __align__(16) float zsh[32][Dd];
    int r0 = blockIdx.x * 32;
    int tid = threadIdx.x;
    for (int idx = tid; idx < 32 * FIN; idx += 256) {
        int r = idx / FIN, c = idx % FIN;
        int row = r0 + r;
        xsh[r][c] = (row < Nn) ? x0[row * FIN + c] : 0.f;
    }
    __syncthreads();
    for (int idx = tid; idx < 32 * Dd; idx += 256) {
        int r = idx / Dd, d = idx % Dd;
        float a = 0.f;
#pragma unroll
        for (int k = 0; k < FIN; k++) a += xsh[r][k] * Wenc[k * (Dd + 3) + d];
        float v = tanhf(a) * SCALE;
        zsh[r][d] = v;
        int row = r0 + r;
        if (row < Nn) g_z[row * Dd + d] = v;
    }
    __syncthreads();
    for (int idx = tid; idx < 32 * Dd; idx += 256) {
        int r = idx / Dd, d = idx % Dd;
        int row = r0 + r;
        if (row < Nn) {
            float a = 0.f;
#pragma unroll
            for (int k = 0; k < Dd; k++) a += zsh[r][k] * Wemb[k * Dd + d];
            g_XW1[row * Dd + d] = a;
        }
    }
    // P1 column for this thread, packed f32x2, fused column-softmax partial sums
    int p = tid;
    u64 wp[32];
#pragma unroll
    for (int kk = 0; kk < 32; kk++)
        wp[kk] = pk2(Wp[(2 * kk) * P1n + p], Wp[(2 * kk + 1) * P1n + p]);
    float se = 0.f, sev = 0.f;
    int rmax = Nn - r0; if (rmax > 32) rmax = 32;
    for (int r = 0; r < rmax; r++) {
        u64 acc = 0ull;
        const ulonglong2* zz = (const ulonglong2*)zsh[r];
#pragma unroll
        for (int q = 0; q < 16; q++) {
            ulonglong2 zp = zz[q];
            fma2(acc, zp.x, wp[2 * q]);
            fma2(acc, zp.y, wp[2 * q + 1]);
        }
        float v = sum2(acc) * SCALE;
        float e = __expf(v);
        g_E1[(r0 + r) * P1n + p] = e;
        se += e; sev += e * v;
    }
    atomicAdd(&g_colE[p], se);
    atomicAdd(&g_colEV[p], sev);
}

// ---------------- kernel 4: sparse gathers (A@XW1 -> ze1, A@E1 -> AS1) + finalize ----------------
__global__ void gather_fused() {
    if (blockIdx.x == (Nn / 4)) {  // finalize block: invZ + level-1 entropy
        int p = threadIdx.x;
        float Z = g_colE[p];
        float iz = 1.f / Z;
        g_invZ[p] = iz;
        float ent = __logf(Z) - g_colEV[p] * iz;
        __shared__ float sh[8];
#pragma unroll
        for (int off = 16; off; off >>= 1) ent += __shfl_down_sync(0xffffffffu, ent, off);
        if ((p & 31) == 0) sh[p >> 5] = ent;
        __syncthreads();
        if (p == 0) {
            float s = 0.f;
            for (int w = 0; w < 8; w++) s += sh[w];
            atomicAdd(&g_acc[0], s * (1.f / ((float)Nn * (float)P1n)));
        }
        return;
    }
    int i0 = blockIdx.x * 4;
    int t = threadIdx.x;
    for (int r = 0; r < 4; r++) {
        int i = i0 + r;
        int cn = g_cnt[i]; if (cn > ELLW) cn = ELLW;
        const int* cl = &g_ell[i * ELLW];
        float as = 0.f, ax = 0.f;
        for (int k = 0; k < cn; k++) {
            int j = cl[k];
            as += g_E1[j * P1n + t];
            if (t < Dd) ax += g_XW1[j * Dd + t];
        }
        g_AS1[i * P1n + t] = as;
        if (t < Dd) g_ze1[i * Dd + t] = tanhf(ax);
    }
}

// ---------------- kernel 5: combined pool GEMMs (x1,y1,A2) with split-K + f32x2 ----------------
__global__ void pool_gemm(const float* __restrict__ yin) {
    const int NSPLIT = 29;
    int grp = blockIdx.x / NSPLIT;        // 0: x1/y1; 1..4: A2 col-groups
    int ks = blockIdx.x % NSPLIT;
    const int chunk = (Nn + NSPLIT - 1) / NSPLIT;  // 173
    int rbeg = ks * chunk;
    int rend = rbeg + chunk; if (rend > Nn) rend = Nn;
    int tid = threadIdx.x;
    __shared__ float Ssh[8][P1n];
    __shared__ __align__(16) float Bsh[8][Dd];
    __shared__ float ysh[8];
    __shared__ float izsh[Dd];
    const float* B; int bst, d0;
    if (grp == 0) { B = g_ze1; bst = Dd; d0 = 0; }
    else { B = g_AS1; bst = P1n; d0 = (grp - 1) * Dd; }
    if (grp != 0 && tid < Dd) izsh[tid] = g_invZ[d0 + tid];
    u64 acc2[32];
#pragma unroll
    for (int d = 0; d < 32; d++) acc2[d] = 0ull;
    float accY = 0.f;
    for (int t0 = rbeg; t0 < rend; t0 += 8) {
        __syncthreads();
#pragma unroll
        for (int l = 0; l < 8; l++) {
            int row = t0 + l;
            Ssh[l][tid] = (row < rend) ? g_E1[row * P1n + tid] : 0.f;
        }
        if (tid < 128) {
            int l = tid >> 4, q = tid & 15;
            int row = t0 + l;
            float4 v = make_float4(0.f, 0.f, 0.f, 0.f);
            if (row < rend) v = *(const float4*)&B[row * bst + d0 + q * 4];
            ((float4*)Bsh[l])[q] = v;
        }
        if (grp == 0 && tid < 8) {
            int row = t0 + tid;
            ysh[tid] = (row < rend) ? yin[row] : 0.f;
        }
        __syncthreads();
#pragma unroll
        for (int r = 0; r < 8; r++) {
            float a = Ssh[r][tid];
            u64 ap = pk2(a, a);
            if (grp == 0) accY += a * ysh[r];
            const ulonglong2* bb = (const ulonglong2*)Bsh[r];
#pragma unroll
            for (int q = 0; q < 16; q++) {
                ulonglong2 b = bb[q];
                fma2(acc2[2 * q], b.x, ap);
                fma2(acc2[2 * q + 1], b.y, ap);
            }
        }
    }
    float iz = g_invZ[tid];
    if (grp == 0) {
        const float m = iz * ((float)P1n / (float)Nn);
#pragma unroll
        for (int q = 0; q < 32; q++) {
            float a, b; unpk(acc2[q], a, b);
            atomicAdd(&g_x1[tid * Dd + 2 * q], a * m);
            atomicAdd(&g_x1[tid * Dd + 2 * q + 1], b * m);
        }
        atomicAdd(&g_y1[tid], accY * m);
    } else {
#pragma unroll
        for (int q = 0; q < 32; q++) {
            float a, b; unpk(acc2[q], a, b);
            atomicAdd(&g_A2[tid * P1n + d0 + 2 * q], a * iz * izsh[2 * q]);
            atomicAdd(&g_A2[tid * P1n + d0 + 2 * q + 1], b * iz * izsh[2 * q + 1]);
        }
    }
}

// ---------------- kernel 6: level-2 softmax (blocks 0..31) + ze2 via (A2@x1)@Wemb2 (blocks 32..95) ----------------
__global__ void level2a(const float* __restrict__ Wp2, const float* __restrict__ Wemb2) {
    int b = blockIdx.x;
    int tid = threadIdx.x;
    if (b < P2n) {
        __shared__ float wcol[Dd];
        __shared__ float shE[8], shEV[8];
        __shared__ float sZ;
        if (tid < Dd) wcol[tid] = Wp2[tid * P2n + b];
        __syncthreads();
        float a = 0.f;
#pragma unroll
        for (int k = 0; k < Dd; k++) a += g_x1[tid * Dd + k] * wcol[k];
        float v = a * SCALE;
        float e = __expf(v);
        float se = e, sev = e * v;
#pragma unroll
        for (int off = 16; off; off >>= 1) {
            se += __shfl_down_sync(0xffffffffu, se, off);
            sev += __shfl_down_sync(0xffffffffu, sev, off);
        }
        if ((tid & 31) == 0) { shE[tid >> 5] = se; shEV[tid >> 5] = sev; }
        __syncthreads();
        if (tid == 0) {
            float Z = 0.f, EV = 0.f;
            for (int w = 0; w < 8; w++) { Z += shE[w]; EV += shEV[w]; }
            sZ = Z;
            atomicAdd(&g_acc[0], (__logf(Z) - EV / Z) * (1.f / ((float)P1n * (float)P2n)));
        }
        __syncthreads();
        g_S2[tid * P2n + b] = e / sZ;
    } else {
        int rb = (b - P2n) * 4;
        __shared__ float Ash[4][P1n];
        __shared__ __align__(16) float Tsh[4][Dd];
        for (int idx = tid; idx < 4 * P1n; idx += 256) {
            int r = idx >> 8, k = idx & 255;
            Ash[r][k] = g_A2[(rb + r) * P1n + k];
        }
        __syncthreads();
        int r = tid >> 6, d = tid & 63;
        float a = 0.f;
        for (int k = 0; k < P1n; k++) a += Ash[r][k] * g_x1[k * Dd + d];
        Tsh[r][d] = a;
        __syncthreads();
        float s = 0.f;
#pragma unroll
        for (int j = 0; j < Dd; j++) s += Tsh[r][j] * Wemb2[j * Dd + d];
        g_ze2[(rb + r) * Dd + d] = tanhf(s);
    }
}

// ---------------- kernel 7: decoder + losses + inline level-2 pooling + final reduce ----------------
__global__ void decoder(const float* __restrict__ W1, const float* __restrict__ W2,
                        const float* __restrict__ b2, const float* __restrict__ yin,
                        float* __restrict__ out) {
    int base = blockIdx.x * 8;
    int h = threadIdx.x;
    __shared__ __align__(16) float zsh[8][Dd];
    __shared__ float ysh[8];
    __shared__ float2 sUR[8][8];
    __shared__ float pd[8], pr2[8];
    if (base >= Nn + P1n) {
        // inline pool2: x2 row p = (32/256) * sum_k S2[k,p] * ze2[k,:]
        const float scl = (float)P2n / (float)P1n;
        for (int idx = h; idx < 8 * Dd; idx += 256) {
            int r = idx >> 6, j = idx & 63;
            int p = base + r - (Nn + P1n);
            float a = 0.f;
            for (int k = 0; k < P1n; k++) a += g_S2[k * P2n + p] * g_ze2[k * Dd + j];
            zsh[r][j] = a * scl;
        }
        if (h < 8) {
            int p = base + h - (Nn + P1n);
            float a = 0.f;
            for (int k = 0; k < P1n; k++) a += g_S2[k * P2n + p] * g_y1[k];
            ysh[h] = a * scl;
        }
    } else {
        for (int idx = h; idx < 8 * Dd; idx += 256) {
            int r = idx >> 6, j = idx & 63;
            int m = base + r;
            zsh[r][j] = (m < Nn) ? g_z[m * Dd + j] : g_x1[(m - Nn) * Dd + j];
        }
        if (h < 8) {
            int m = base + h;
            ysh[h] = (m < Nn) ? yin[m] : g_y1[m - Nn];
        }
    }
    __syncthreads();
    float c = g_c[h];
    u64 acc2[8];
#pragma unroll
    for (int r = 0; r < 8; r++) acc2[r] = 0ull;
#pragma unroll 8
    for (int jj = 0; jj < 32; jj++) {
        u64 wp = pk2(W1[(9 + 2 * jj) * Hh + h], W1[(10 + 2 * jj) * Hh + h]);
#pragma unroll
        for (int r = 0; r < 8; r++) {
            u64 zp = *(const u64*)&zsh[r][2 * jj];
            fma2(acc2[r], zp, wp);
        }
    }
    float w2 = W2[h], w0 = g_w0[h], q = g_q[h];
    int wid = h >> 5, lane = h & 31;
#pragma unroll
    for (int r = 0; r < 8; r++) {
        float a = c + sum2(acc2[r]);
        float th = tanhf(a);
        float s = 1.f - th * th;
        float up = w2 * th;
        float rp = w2 * s * (w0 + 2.f * th * q);
#pragma unroll
        for (int off = 16; off; off >>= 1) {
            up += __shfl_down_sync(0xffffffffu, up, off);
            rp += __shfl_down_sync(0xffffffffu, rp, off);
        }
        if (lane == 0) sUR[r][wid] = make_float2(up, rp);
    }
    __syncthreads();
    if (h < 8) {
        float u = b2[0], rr = 0.f;
        for (int w = 0; w < 8; w++) { float2 v = sUR[h][w]; u += v.x; rr += v.y; }
        float dd = u - ysh[h];
        pd[h] = dd * dd;
        pr2[h] = rr * rr;
    }
    __syncthreads();
    if (h == 0) {
        float s1 = 0.f, s2 = 0.f;
        for (int r = 0; r < 8; r++) { s1 += pd[r]; s2 += pr2[r]; }
        atomicAdd(&g_acc[1], s1);
        atomicAdd(&g_acc[2], s2);
        __threadfence();
        unsigned int old = atomicAdd(&g_done, 1u);
        if (old == gridDim.x - 1) {
            float a0 = *(volatile float*)&g_acc[0];
            float a1 = *(volatile float*)&g_acc[1];
            float a2 = *(volatile float*)&g_acc[2];
            out[0] = a1 * (1.f / (float)Mm) + a2 * (1.f / (float)Mm) + a0;
        }
    }
}

// ---------------- launch ----------------
extern "C" void kernel_launch(void* const* d_in, const int* in_sizes, int n_in,
                              void* d_out, int out_size) {
    const float* x0 = (const float*)d_in[0];
    const int* adj = (const int*)d_in[1];
    const float* t = (const float*)d_in[2];
    const float* y = (const float*)d_in[3];
    const float* Wenc = (const float*)d_in[4];
    const float* Wp1 = (const float*)d_in[5];
    const float* Wp2 = (const float*)d_in[6];
    const float* Wemb1 = (const float*)d_in[7];
    const float* Wemb2 = (const float*)d_in[8];
    const float* W1 = (const float*)d_in[9];
    const float* b1 = (const float*)d_in[10];
    const float* W2 = (const float*)d_in[11];
    const float* b2 = (const float*)d_in[12];
    float* out = (float*)d_out;

    zero_all<<<256, 256>>>(t, W1, b1);
    edge_build<<<(Ee + 255) / 256, 256>>>(adj);
    encode_fused<<<(Nn + 31) / 32, 256>>>(x0, Wenc, Wemb1, Wp1);
    gather_fused<<<Nn / 4 + 1, 256>>>();
    pool_gemm<<<145, 256>>>(y);
    level2a<<<96, 256>>>(Wp2, Wemb2);
    decoder<<<Mm / 8, 256>>>(W1, W2, b2, y, out);
}

// round 6
// speedup vs baseline: 1.6143x; 1.4272x over previous
#include <cuda_runtime.h>

#define Nn 5000
#define Ee 80000
#define FIN 32
#define Dd 64
#define P1n 256
#define P2n 32
#define Hh 256
#define Mm 5288
#define ELLW 128
#define SCALE 1.4763057f

typedef unsigned long long u64;

// ---------------- packed f32x2 helpers ----------------
__device__ __forceinline__ void fma2(u64& acc, u64 b, u64 a) {
    asm("fma.rn.f32x2 %0, %1, %2, %0;" : "+l"(acc) : "l"(b), "l"(a));
}
__device__ __forceinline__ u64 pk2(float lo, float hi) {
    u64 r; asm("mov.b64 %0, {%1, %2};" : "=l"(r) : "f"(lo), "f"(hi)); return r;
}
__device__ __forceinline__ void unpk(u64 v, float& a, float& b) {
    asm("mov.b64 {%0, %1}, %2;" : "=f"(a), "=f"(b) : "l"(v));
}
__device__ __forceinline__ float sum2(u64 v) {
    float a, b; unpk(v, a, b); return a + b;
}

// ---------------- scratch (static, no allocation) ----------------
__device__ __align__(16) float g_z[Nn * Dd];
__device__ __align__(16) float g_XW1[Nn * Dd];
__device__ __align__(16) float g_E1[Nn * P1n];    // exp(P1) unnormalized
__device__ __align__(16) float g_AS1[Nn * P1n];   // A @ E1 (unscaled)
__device__ __align__(16) float g_ze1[Nn * Dd];
__device__ unsigned int g_bitmap[(Nn * Nn + 31) / 32];
__device__ int g_cnt[Nn];
__device__ int g_ell[Nn * ELLW];
__device__ float g_colE[P1n], g_colEV[P1n], g_invZ[P1n];
__device__ __align__(16) float g_x1[P1n * Dd];
__device__ float g_y1[P1n];
__device__ __align__(16) float g_A2[P1n * P1n];
__device__ __align__(16) float g_S2[P1n * P2n];
__device__ __align__(16) float g_ze2[P1n * Dd];
__device__ float g_c[Hh], g_q[Hh], g_w0[Hh];
__device__ float g_acc[4];   // [0]=ent, [1]=sum(u-y)^2, [2]=sum(res^2)
__device__ unsigned int g_done;

// ---------------- kernel 1: zero accumulators + decoder prep ----------------
__global__ void zero_all(const float* __restrict__ t, const float* __restrict__ W1,
                         const float* __restrict__ b1) {
    int i = blockIdx.x * blockDim.x + threadIdx.x;
    int st = gridDim.x * blockDim.x;
    const int BW = (Nn * Nn + 31) / 32;       // 781250
    const int BW4 = BW / 4;                    // 195312
    uint4* bm4 = (uint4*)g_bitmap;
    uint4 z4 = make_uint4(0u, 0u, 0u, 0u);
    for (int k = i; k < BW4; k += st) bm4[k] = z4;
    if (i < BW - BW4 * 4) g_bitmap[BW4 * 4 + i] = 0u;
    for (int k = i; k < Nn; k += st) g_cnt[k] = 0;
    for (int k = i; k < P1n; k += st) { g_colE[k] = 0.f; g_colEV[k] = 0.f; g_y1[k] = 0.f; }
    for (int k = i; k < P1n * Dd; k += st) g_x1[k] = 0.f;
    for (int k = i; k < P1n * P1n; k += st) g_A2[k] = 0.f;
    if (i == 0) { g_acc[0] = g_acc[1] = g_acc[2] = g_acc[3] = 0.f; g_done = 0u; }
    // decoder precompute (block 0, threads 0..255 = h)
    if (blockIdx.x == 0) {
        int h = threadIdx.x;
        float t0 = t[0];
        float tx[6];
        tx[0] = t0 * 1e-2f;
        tx[1] = t0 * 1e-3f;
        tx[2] = t0 * 1e-4f;
        tx[3] = logf(t0 * 100.f + 1.f);
        tx[4] = logf(t0 * 10.f + 1.f);
        tx[5] = logf(t0 + 1.f);
        float c = b1[h];
#pragma unroll
        for (int k = 0; k < 6; k++) c += W1[k * Hh + h] * tx[k];
        float q = 0.f;
#pragma unroll
        for (int k = 1; k < 9; k++) { float w = W1[k * Hh + h]; q += w * w; }
        g_c[h] = c; g_q[h] = q; g_w0[h] = W1[h];
    }
}

// ---------------- kernel 2: edge dedup + ELL build ----------------
__global__ void edge_build(const int* __restrict__ adj) {
    int e = blockIdx.x * blockDim.x + threadIdx.x;
    if (e >= Ee) return;
    int r0 = adj[e], r1 = adj[Ee + e];
    unsigned int key = (unsigned int)r0 * (unsigned int)Nn + (unsigned int)r1;
    unsigned int bit = 1u << (key & 31u);
    unsigned int old = atomicOr(&g_bitmap[key >> 5], bit);
    if ((old & bit) == 0u) {
        int pos = atomicAdd(&g_cnt[r0], 1);
        if (pos < ELLW) g_ell[r0 * ELLW + pos] = r1;
    }
}

// ---------------- kernel 3: encode + XW1 + exp(P1) + column sums ----------------
__global__ void encode_fused(const float* __restrict__ x0, const float* __restrict__ Wenc,
                             const float* __restrict__ Wemb, const float* __restrict__ Wp) {
    __shared__ float xsh[32][FIN];
    __shared__ __align__(16) float zsh[32][Dd];
    int r0 = blockIdx.x * 32;
    int tid = threadIdx.x;
    for (int idx = tid; idx < 32 * FIN; idx += 256) {
        int r = idx / FIN, c = idx % FIN;
        int row = r0 + r;
        xsh[r][c] = (row < Nn) ? x0[row * FIN + c] : 0.f;
    }
    __syncthreads();
    for (int idx = tid; idx < 32 * Dd; idx += 256) {
        int r = idx / Dd, d = idx % Dd;
        float a = 0.f;
#pragma unroll
        for (int k = 0; k < FIN; k++) a += xsh[r][k] * Wenc[k * (Dd + 3) + d];
        float v = tanhf(a) * SCALE;
        zsh[r][d] = v;
        int row = r0 + r;
        if (row < Nn) g_z[row * Dd + d] = v;
    }
    __syncthreads();
    for (int idx = tid; idx < 32 * Dd; idx += 256) {
        int r = idx / Dd, d = idx % Dd;
        int row = r0 + r;
        if (row < Nn) {
            float a = 0.f;
#pragma unroll
            for (int k = 0; k < Dd; k++) a += zsh[r][k] * Wemb[k * Dd + d];
            g_XW1[row * Dd + d] = a;
        }
    }
    // P1 column for this thread, packed f32x2, fused column-softmax partial sums
    int p = tid;
    u64 wp[32];
#pragma unroll
    for (int kk = 0; kk < 32; kk++)
        wp[kk] = pk2(Wp[(2 * kk) * P1n + p], Wp[(2 * kk + 1) * P1n + p]);
    float se = 0.f, sev = 0.f;
    int rmax = Nn - r0; if (rmax > 32) rmax = 32;
    for (int r = 0; r < rmax; r++) {
        u64 acc = 0ull;
        const ulonglong2* zz = (const ulonglong2*)zsh[r];
#pragma unroll
        for (int q = 0; q < 16; q++) {
            ulonglong2 zp = zz[q];
            fma2(acc, zp.x, wp[2 * q]);
            fma2(acc, zp.y, wp[2 * q + 1]);
        }
        float v = sum2(acc) * SCALE;
        float e = __expf(v);
        g_E1[(r0 + r) * P1n + p] = e;
        se += e; sev += e * v;
    }
    atomicAdd(&g_colE[p], se);
    atomicAdd(&g_colEV[p], sev);
}

// ---------------- kernel 4: sparse gathers (A@XW1 -> ze1, A@E1 -> AS1) + finalize ----------------
__global__ void gather_fused() {
    if (blockIdx.x == (Nn / 4)) {  // finalize block: invZ + level-1 entropy
        int p = threadIdx.x;
        float Z = g_colE[p];
        float iz = 1.f / Z;
        g_invZ[p] = iz;
        float ent = __logf(Z) - g_colEV[p] * iz;
        __shared__ float sh[8];
#pragma unroll
        for (int off = 16; off; off >>= 1) ent += __shfl_down_sync(0xffffffffu, ent, off);
        if ((p & 31) == 0) sh[p >> 5] = ent;
        __syncthreads();
        if (p == 0) {
            float s = 0.f;
            for (int w = 0; w < 8; w++) s += sh[w];
            atomicAdd(&g_acc[0], s * (1.f / ((float)Nn * (float)P1n)));
        }
        return;
    }
    int i0 = blockIdx.x * 4;
    int t = threadIdx.x;
    for (int r = 0; r < 4; r++) {
        int i = i0 + r;
        int cn = g_cnt[i]; if (cn > ELLW) cn = ELLW;
        const int* cl = &g_ell[i * ELLW];
        float as = 0.f, ax = 0.f;
        for (int k = 0; k < cn; k++) {
            int j = cl[k];
            as += g_E1[j * P1n + t];
            if (t < Dd) ax += g_XW1[j * Dd + t];
        }
        g_AS1[i * P1n + t] = as;
        if (t < Dd) g_ze1[i * Dd + t] = tanhf(ax);
    }
}

// ---------------- kernel 5: combined pool GEMMs (x1,y1,A2) with split-K + f32x2 ----------------
__global__ void pool_gemm(const float* __restrict__ yin) {
    const int NSPLIT = 29;
    int grp = blockIdx.x / NSPLIT;        // 0: x1/y1; 1..4: A2 col-groups
    int ks = blockIdx.x % NSPLIT;
    const int chunk = (Nn + NSPLIT - 1) / NSPLIT;  // 173
    int rbeg = ks * chunk;
    int rend = rbeg + chunk; if (rend > Nn) rend = Nn;
    int tid = threadIdx.x;
    __shared__ float Ssh[8][P1n];
    __shared__ __align__(16) float Bsh[8][Dd];
    __shared__ float ysh[8];
    __shared__ float izsh[Dd];
    const float* B; int bst, d0;
    if (grp == 0) { B = g_ze1; bst = Dd; d0 = 0; }
    else { B = g_AS1; bst = P1n; d0 = (grp - 1) * Dd; }
    if (grp != 0 && tid < Dd) izsh[tid] = g_invZ[d0 + tid];
    u64 acc2[32];
#pragma unroll
    for (int d = 0; d < 32; d++) acc2[d] = 0ull;
    float accY = 0.f;
    for (int t0 = rbeg; t0 < rend; t0 += 8) {
        __syncthreads();
#pragma unroll
        for (int l = 0; l < 8; l++) {
            int row = t0 + l;
            Ssh[l][tid] = (row < rend) ? g_E1[row * P1n + tid] : 0.f;
        }
        if (tid < 128) {
            int l = tid >> 4, q = tid & 15;
            int row = t0 + l;
            float4 v = make_float4(0.f, 0.f, 0.f, 0.f);
            if (row < rend) v = *(const float4*)&B[row * bst + d0 + q * 4];
            ((float4*)Bsh[l])[q] = v;
        }
        if (grp == 0 && tid < 8) {
            int row = t0 + tid;
            ysh[tid] = (row < rend) ? yin[row] : 0.f;
        }
        __syncthreads();
#pragma unroll
        for (int r = 0; r < 8; r++) {
            float a = Ssh[r][tid];
            u64 ap = pk2(a, a);
            if (grp == 0) accY += a * ysh[r];
            const ulonglong2* bb = (const ulonglong2*)Bsh[r];
#pragma unroll
            for (int q = 0; q < 16; q++) {
                ulonglong2 b = bb[q];
                fma2(acc2[2 * q], b.x, ap);
                fma2(acc2[2 * q + 1], b.y, ap);
            }
        }
    }
    float iz = g_invZ[tid];
    if (grp == 0) {
        const float m = iz * ((float)P1n / (float)Nn);
#pragma unroll
        for (int q = 0; q < 32; q++) {
            float a, b; unpk(acc2[q], a, b);
            atomicAdd(&g_x1[tid * Dd + 2 * q], a * m);
            atomicAdd(&g_x1[tid * Dd + 2 * q + 1], b * m);
        }
        atomicAdd(&g_y1[tid], accY * m);
    } else {
#pragma unroll
        for (int q = 0; q < 32; q++) {
            float a, b; unpk(acc2[q], a, b);
            atomicAdd(&g_A2[tid * P1n + d0 + 2 * q], a * iz * izsh[2 * q]);
            atomicAdd(&g_A2[tid * P1n + d0 + 2 * q + 1], b * iz * izsh[2 * q + 1]);
        }
    }
}

// ---------------- kernel 6: level-2 softmax (blocks 0..31) + ze2 via (A2@x1)@Wemb2 (blocks 32..95) ----------------
__global__ void level2a(const float* __restrict__ Wp2, const float* __restrict__ Wemb2) {
    int b = blockIdx.x;
    int tid = threadIdx.x;
    if (b < P2n) {
        __shared__ float wcol[Dd];
        __shared__ float shE[8], shEV[8];
        __shared__ float sZ;
        if (tid < Dd) wcol[tid] = Wp2[tid * P2n + b];
        __syncthreads();
        float a = 0.f;
#pragma unroll
        for (int k = 0; k < Dd; k++) a += g_x1[tid * Dd + k] * wcol[k];
        float v = a * SCALE;
        float e = __expf(v);
        float se = e, sev = e * v;
#pragma unroll
        for (int off = 16; off; off >>= 1) {
            se += __shfl_down_sync(0xffffffffu, se, off);
            sev += __shfl_down_sync(0xffffffffu, sev, off);
        }
        if ((tid & 31) == 0) { shE[tid >> 5] = se; shEV[tid >> 5] = sev; }
        __syncthreads();
        if (tid == 0) {
            float Z = 0.f, EV = 0.f;
            for (int w = 0; w < 8; w++) { Z += shE[w]; EV += shEV[w]; }
            sZ = Z;
            atomicAdd(&g_acc[0], (__logf(Z) - EV / Z) * (1.f / ((float)P1n * (float)P2n)));
        }
        __syncthreads();
        g_S2[tid * P2n + b] = e / sZ;
    } else {
        int rb = (b - P2n) * 4;
        __shared__ float Ash[4][P1n];
        __shared__ __align__(16) float Tsh[4][Dd];
        for (int idx = tid; idx < 4 * P1n; idx += 256) {
            int r = idx >> 8, k = idx & 255;
            Ash[r][k] = g_A2[(rb + r) * P1n + k];
        }
        __syncthreads();
        int r = tid >> 6, d = tid & 63;
        float a = 0.f;
        for (int k = 0; k < P1n; k++) a += Ash[r][k] * g_x1[k * Dd + d];
        Tsh[r][d] = a;
        __syncthreads();
        float s = 0.f;
#pragma unroll
        for (int j = 0; j < Dd; j++) s += Tsh[r][j] * Wemb2[j * Dd + d];
        g_ze2[(rb + r) * Dd + d] = tanhf(s);
    }
}

// ---------------- kernel 7: decoder + losses + inline level-2 pooling + final reduce ----------------
__global__ void decoder(const float* __restrict__ W1, const float* __restrict__ W2,
                        const float* __restrict__ b2, const float* __restrict__ yin,
                        float* __restrict__ out) {
    int base = blockIdx.x * 8;
    int h = threadIdx.x;
    __shared__ __align__(16) float zsh[8][Dd];
    __shared__ float ysh[8];
    __shared__ float2 sUR[8][8];
    __shared__ float pd[8], pr2[8];
    if (base >= Nn + P1n) {
        // inline pool2: x2 row p = (32/256) * sum_k S2[k,p] * ze2[k,:]
        const float scl = (float)P2n / (float)P1n;
        for (int idx = h; idx < 8 * Dd; idx += 256) {
            int r = idx >> 6, j = idx & 63;
            int p = base + r - (Nn + P1n);
            float a = 0.f;
            for (int k = 0; k < P1n; k++) a += g_S2[k * P2n + p] * g_ze2[k * Dd + j];
            zsh[r][j] = a * scl;
        }
        if (h < 8) {
            int p = base + h - (Nn + P1n);
            float a = 0.f;
            for (int k = 0; k < P1n; k++) a += g_S2[k * P2n + p] * g_y1[k];
            ysh[h] = a * scl;
        }
    } else {
        for (int idx = h; idx < 8 * Dd; idx += 256) {
            int r = idx >> 6, j = idx & 63;
            int m = base + r;
            zsh[r][j] = (m < Nn) ? g_z[m * Dd + j] : g_x1[(m - Nn) * Dd + j];
        }
        if (h < 8) {
            int m = base + h;
            ysh[h] = (m < Nn) ? yin[m] : g_y1[m - Nn];
        }
    }
    __syncthreads();
    float c = g_c[h];
    u64 acc2[8];
#pragma unroll
    for (int r = 0; r < 8; r++) acc2[r] = 0ull;
#pragma unroll 8
    for (int jj = 0; jj < 32; jj++) {
        u64 wp = pk2(W1[(9 + 2 * jj) * Hh + h], W1[(10 + 2 * jj) * Hh + h]);
#pragma unroll
        for (int r = 0; r < 8; r++) {
            u64 zp = *(const u64*)&zsh[r][2 * jj];
            fma2(acc2[r], zp, wp);
        }
    }
    float w2 = W2[h], w0 = g_w0[h], q = g_q[h];
    int wid = h >> 5, lane = h & 31;
#pragma unroll
    for (int r = 0; r < 8; r++) {
        float a = c + sum2(acc2[r]);
        float th = tanhf(a);
        float s = 1.f - th * th;
        float up = w2 * th;
        float rp = w2 * s * (w0 + 2.f * th * q);
#pragma unroll
        for (int off = 16; off; off >>= 1) {
            up += __shfl_down_sync(0xffffffffu, up, off);
            rp += __shfl_down_sync(0xffffffffu, rp, off);
        }
        if (lane == 0) sUR[r][wid] = make_float2(up, rp);
    }
    __syncthreads();
    if (h < 8) {
        float u = b2[0], rr = 0.f;
        for (int w = 0; w < 8; w++) { float2 v = sUR[h][w]; u += v.x; rr += v.y; }
        float dd = u - ysh[h];
        pd[h] = dd * dd;
        pr2[h] = rr * rr;
    }
    __syncthreads();
    if (h == 0) {
        float s1 = 0.f, s2 = 0.f;
        for (int r = 0; r < 8; r++) { s1 += pd[r]; s2 += pr2[r]; }
        atomicAdd(&g_acc[1], s1);
        atomicAdd(&g_acc[2], s2);
        __threadfence();
        unsigned int old = atomicAdd(&g_done, 1u);
        if (old == gridDim.x - 1) {
            float a0 = *(volatile float*)&g_acc[0];
            float a1 = *(volatile float*)&g_acc[1];
            float a2 = *(volatile float*)&g_acc[2];
            out[0] = a1 * (1.f / (float)Mm) + a2 * (1.f / (float)Mm) + a0;
        }
    }
}

// ---------------- launch ----------------
extern "C" void kernel_launch(void* const* d_in, const int* in_sizes, int n_in,
                              void* d_out, int out_size) {
    const float* x0 = (const float*)d_in[0];
    const int* adj = (const int*)d_in[1];
    const float* t = (const float*)d_in[2];
    const float* y = (const float*)d_in[3];
    const float* Wenc = (const float*)d_in[4];
    const float* Wp1 = (const float*)d_in[5];
    const float* Wp2 = (const float*)d_in[6];
    const float* Wemb1 = (const float*)d_in[7];
    const float* Wemb2 = (const float*)d_in[8];
    const float* W1 = (const float*)d_in[9];
    const float* b1 = (const float*)d_in[10];
    const float* W2 = (const float*)d_in[11];
    const float* b2 = (const float*)d_in[12];
    float* out = (float*)d_out;

    zero_all<<<256, 256>>>(t, W1, b1);
    edge_build<<<(Ee + 255) / 256, 256>>>(adj);
    encode_fused<<<(Nn + 31) / 32, 256>>>(x0, Wenc, Wemb1, Wp1);
    gather_fused<<<Nn / 4 + 1, 256>>>();
    pool_gemm<<<145, 256>>>(y);
    level2a<<<96, 256>>>(Wp2, Wemb2);
    decoder<<<Mm / 8, 256>>>(W1, W2, b2, y, out);
}